// round 6
// baseline (speedup 1.0000x reference)
#include <cuda_runtime.h>

#define NB   4
#define NP   4096
#define TILE 128
#define RT   8
#define CT   8
#define NMIN (2 * NB * NP)   // 32768 partial mins: [gt-mins | coord-mins]

// Scratch (device global — no allocation allowed in kernel_launch).
__device__ unsigned g_minbits[NMIN];

__global__ void init_min_kernel() {
    int i = blockIdx.x * blockDim.x + threadIdx.x;
    if (i < NMIN) g_minbits[i] = 0x7F800000u;  // +inf bits
}

__global__ __launch_bounds__(256) void chamfer_tile_kernel(
    const float* __restrict__ coord, const float* __restrict__ gt)
{
    __shared__ float sgx[TILE], sgy[TILE], sgz[TILE];
    __shared__ float scx[TILE], scy[TILE], scz[TILE];
    __shared__ unsigned srowmin[TILE];
    __shared__ unsigned scolmin[TILE];

    const int b    = blockIdx.z;
    const int row0 = blockIdx.y * TILE;   // gt points (rows)
    const int col0 = blockIdx.x * TILE;   // coord points (cols)
    const int t    = threadIdx.x;

    // Stage both 128-point tiles into SoA shared memory (tiny: 3 KB).
    if (t < TILE) {
        const float* p = gt + (size_t)(b * NP + row0 + t) * 3;
        sgx[t] = p[0]; sgy[t] = p[1]; sgz[t] = p[2];
        scolmin[t] = 0x7F800000u;
    } else {
        const int u = t - TILE;
        const float* p = coord + (size_t)(b * NP + col0 + u) * 3;
        scx[u] = p[0]; scy[u] = p[1]; scz[u] = p[2];
    }
    __syncthreads();

    const int ty = t >> 4;     // 0..15 -> row group
    const int tx = t & 15;     // 0..15 -> col group

    float rx[RT], ry[RT], rz[RT];
    float cx[CT], cy[CT], cz[CT];
#pragma unroll
    for (int i = 0; i < RT; i++) {
        const int r = ty * RT + i;
        rx[i] = sgx[r]; ry[i] = sgy[r]; rz[i] = sgz[r];
    }
#pragma unroll
    for (int j = 0; j < CT; j++) {
        const int c = tx * CT + j;
        cx[j] = scx[c]; cy[j] = scy[c]; cz[j] = scz[c];
    }

    const float INF = __int_as_float(0x7F800000);
    float rmin[RT], cmin[CT];
#pragma unroll
    for (int i = 0; i < RT; i++) rmin[i] = INF;
#pragma unroll
    for (int j = 0; j < CT; j++) cmin[j] = INF;

    // 8x8 register tile of squared distances; each distance feeds BOTH mins.
#pragma unroll
    for (int i = 0; i < RT; i++) {
#pragma unroll
        for (int j = 0; j < CT; j++) {
            const float dx = rx[i] - cx[j];
            const float dy = ry[i] - cy[j];
            const float dz = rz[i] - cz[j];
            float d = dx * dx;
            d = fmaf(dy, dy, d);
            d = fmaf(dz, dz, d);
            rmin[i] = fminf(rmin[i], d);
            cmin[j] = fminf(cmin[j], d);
        }
    }

    // Row mins: reduce across tx (16 lanes, stays within the warp half).
#pragma unroll
    for (int i = 0; i < RT; i++) {
        float v = rmin[i];
        v = fminf(v, __shfl_xor_sync(0xFFFFFFFFu, v, 1));
        v = fminf(v, __shfl_xor_sync(0xFFFFFFFFu, v, 2));
        v = fminf(v, __shfl_xor_sync(0xFFFFFFFFu, v, 4));
        v = fminf(v, __shfl_xor_sync(0xFFFFFFFFu, v, 8));
        rmin[i] = v;
    }
    if (tx == 0) {
#pragma unroll
        for (int i = 0; i < RT; i++)
            srowmin[ty * RT + i] = __float_as_uint(rmin[i]);  // unique slot per ty
    }

    // Col mins: fold the warp's two ty values, then smem atomicMin across warps.
#pragma unroll
    for (int j = 0; j < CT; j++)
        cmin[j] = fminf(cmin[j], __shfl_xor_sync(0xFFFFFFFFu, cmin[j], 16));
    if ((t & 16) == 0) {
#pragma unroll
        for (int j = 0; j < CT; j++)
            atomicMin(&scolmin[tx * CT + j], __float_as_uint(cmin[j]));
    }
    __syncthreads();

    // Publish partial mins (uint-bit min == float min for nonnegative values).
    if (t < TILE) {
        atomicMin(&g_minbits[b * NP + row0 + t], srowmin[t]);
    } else {
        const int u = t - TILE;
        atomicMin(&g_minbits[NB * NP + b * NP + col0 + u], scolmin[u]);
    }
}

__global__ __launch_bounds__(1024) void reduce_kernel(float* __restrict__ out) {
    __shared__ float ssum[32];
    const int t = threadIdx.x;
    float s = 0.0f;
    for (int i = t; i < NMIN; i += 1024)
        s += __uint_as_float(g_minbits[i]);
#pragma unroll
    for (int m = 16; m; m >>= 1)
        s += __shfl_xor_sync(0xFFFFFFFFu, s, m);
    if ((t & 31) == 0) ssum[t >> 5] = s;
    __syncthreads();
    if (t < 32) {
        float v = ssum[t];
#pragma unroll
        for (int m = 16; m; m >>= 1)
            v += __shfl_xor_sync(0xFFFFFFFFu, v, m);
        if (t == 0)
            // mean(match_coord) + mean(match_gt); B*M == B*N == 16384
            out[0] = v * (1.0f / (float)(NB * NP));
    }
}

extern "C" void kernel_launch(void* const* d_in, const int* in_sizes, int n_in,
                              void* d_out, int out_size) {
    (void)in_sizes; (void)n_in; (void)out_size;
    const float* coord = (const float*)d_in[0];  // [B, N, 3]
    const float* gt    = (const float*)d_in[1];  // [B, M, 3]

    init_min_kernel<<<(NMIN + 255) / 256, 256>>>();
    dim3 grid(NP / TILE, NP / TILE, NB);         // (32, 32, 4) = 4096 blocks
    chamfer_tile_kernel<<<grid, 256>>>(coord, gt);
    reduce_kernel<<<1, 1024>>>((float*)d_out);
}